// round 4
// baseline (speedup 1.0000x reference)
#include <cuda_runtime.h>
#include <cstdint>
#include <math.h>

// Problem constants: B=16, C=512, L=1024 (32x32), 32 groups, 8 heads, ch=64.
#define NB   16
#define NC   512
#define NL   1024
#define NO3  1536

// Scratch (device globals; no allocation allowed)
__device__ float g_ht [(size_t)NB * NL * NC];    // 32 MB groupnorm out, [b][l][c], tf32 bits
__device__ float g_qkv[(size_t)NB * NO3 * NL];   // 96 MB [b][o][l], fp32
__device__ float g_at [(size_t)NB * NL * NC];    // 32 MB attention out, [b][l][c], tf32 bits
__device__ float g_wt [(size_t)(NO3 + NC) * NC]; // 4 MB  weights, tf32 bits

// ===========================================================================
// helpers
// ===========================================================================
__device__ __forceinline__ uint32_t cvt_tf32(float x) {
    uint32_t r;
    asm("cvt.rna.tf32.f32 %0, %1;" : "=r"(r) : "f"(x));
    return r;
}
__device__ __forceinline__ float cvt_tf32f(float x) {
    return __uint_as_float(cvt_tf32(x));
}
__device__ __forceinline__ void mma_tf32(float* d, const uint32_t* a,
                                         const uint32_t* b) {
    asm volatile(
        "mma.sync.aligned.m16n8k8.row.col.f32.tf32.tf32.f32 "
        "{%0,%1,%2,%3}, {%4,%5,%6,%7}, {%8,%9}, {%0,%1,%2,%3};"
        : "+f"(d[0]), "+f"(d[1]), "+f"(d[2]), "+f"(d[3])
        : "r"(a[0]), "r"(a[1]), "r"(a[2]), "r"(a[3]), "r"(b[0]), "r"(b[1]));
}
#define CP_ASYNC16(dst, src) \
    asm volatile("cp.async.cg.shared.global [%0], [%1], 16;" \
                 :: "r"(dst), "l"(src) : "memory")
#define CP_COMMIT() asm volatile("cp.async.commit_group;" ::: "memory")
#define CP_WAIT(n)  asm volatile("cp.async.wait_group %0;" :: "n"(n) : "memory")

__device__ __forceinline__ uint32_t smem_u32(const void* p) {
    uint32_t a;
    asm("{ .reg .u64 t; cvta.to.shared.u64 t, %1; cvt.u32.u64 %0, t; }"
        : "=r"(a) : "l"(p));
    return a;
}

// fast exp on FMA pipe. x <= 0 expected.
__device__ __forceinline__ float fexp(float x) {
    float y = x * 1.4426950408889634f;
    y = fmaxf(y, -125.0f);
    int   e = __float2int_rd(y);
    float f = y - (float)e;
    float p = fmaf(0.0013333558f, f, 0.0096181291f);
    p = fmaf(p, f, 0.0555041087f);
    p = fmaf(p, f, 0.2402264758f);
    p = fmaf(p, f, 0.6931471806f);
    p = fmaf(p, f, 1.0f);
    return p * __int_as_float((e + 127) << 23);
}

// ---------------------------------------------------------------------------
// Pre-round weights to tf32 bits (grid-stride float4).
// ---------------------------------------------------------------------------
__global__ __launch_bounds__(256) void cvt_w_kernel(const float* __restrict__ src,
                                                    float* __restrict__ dst,
                                                    int n4) {
    int i = blockIdx.x * 256 + threadIdx.x;
    if (i < n4) {
        float4 v = ((const float4*)src)[i];
        v.x = cvt_tf32f(v.x); v.y = cvt_tf32f(v.y);
        v.z = cvt_tf32f(v.z); v.w = cvt_tf32f(v.w);
        ((float4*)dst)[i] = v;
    }
}

// ---------------------------------------------------------------------------
// GroupNorm: one block per (batch, group); writes TRANSPOSED h_t[b][l][c],
// tf32-rounded bits (GEMM consumes directly).
// ---------------------------------------------------------------------------
__global__ __launch_bounds__(256) void gn_kernel(const float* __restrict__ x,
                                                 const float* __restrict__ w,
                                                 const float* __restrict__ b) {
    const int blk = blockIdx.x;
    const int bi  = blk >> 5;
    const int g   = blk & 31;
    const float* xg = x + ((size_t)bi * NC + (size_t)g * 16) * NL;
    const int tid = threadIdx.x;

    float s = 0.f, s2 = 0.f;
    for (int v = tid; v < 4096; v += 256) {
        float4 q = *(const float4*)(xg + (size_t)v * 4);
        s  += q.x + q.y + q.z + q.w;
        s2 += q.x*q.x + q.y*q.y + q.z*q.z + q.w*q.w;
    }
    #pragma unroll
    for (int d = 16; d; d >>= 1) {
        s  += __shfl_xor_sync(0xffffffffu, s,  d);
        s2 += __shfl_xor_sync(0xffffffffu, s2, d);
    }
    __shared__ float rs[8], rs2[8];
    __shared__ float smean, srstd;
    if ((tid & 31) == 0) { rs[tid >> 5] = s; rs2[tid >> 5] = s2; }
    __syncthreads();
    if (tid == 0) {
        float ts = 0.f, ts2 = 0.f;
        #pragma unroll
        for (int i = 0; i < 8; i++) { ts += rs[i]; ts2 += rs2[i]; }
        float mean = ts * (1.0f / 16384.0f);
        float var  = ts2 * (1.0f / 16384.0f) - mean * mean;
        smean = mean;
        srstd = rsqrtf(var + 1e-5f);
    }
    __syncthreads();
    const float mean = smean, rstd = srstd;

    const float* xb = x + (size_t)bi * NC * NL;
    float* ob = g_ht + (size_t)bi * NL * NC;
    #pragma unroll
    for (int t = 0; t < 4; t++) {
        int idx = tid + t * 256;
        int l   = (idx & 255) << 2;
        int cb  = g * 16 + ((idx >> 8) << 2);
        float vin[4][4];
        float wc[4], bc[4];
        #pragma unroll
        for (int i = 0; i < 4; i++) {
            *(float4*)vin[i] = *(const float4*)&xb[(size_t)(cb + i) * NL + l];
            wc[i] = w[cb + i] * rstd;
            bc[i] = b[cb + i];
        }
        #pragma unroll
        for (int j = 0; j < 4; j++) {
            float4 o;
            o.x = cvt_tf32f((vin[0][j] - mean) * wc[0] + bc[0]);
            o.y = cvt_tf32f((vin[1][j] - mean) * wc[1] + bc[1]);
            o.z = cvt_tf32f((vin[2][j] - mean) * wc[2] + bc[2]);
            o.w = cvt_tf32f((vin[3][j] - mean) * wc[3] + bc[3]);
            *(float4*)&ob[(size_t)(l + j) * NC + cb] = o;
        }
    }
}

// ---------------------------------------------------------------------------
// mma.sync tf32 GEMM + bias. Inputs are already tf32-rounded bits.
//   Y[bz][m][n] = sum_k W[m][k] * Xt[bz][n][k] + bias[m]
// 128x128 tile, BK=32, 8 warps (4m x 2n), warp tile 32x64.
// cp.async double-buffered; NO cvt in inner loop. AST=36 -> conflict-free LDS.
// ---------------------------------------------------------------------------
#define AST 36
#define TILE_F (128 * AST)
#define GEMM_SMEM (4 * TILE_F * 4)            // 73728 B

__global__ __launch_bounds__(256, 2) void tc_gemm(const float* __restrict__ W,
                                                  const float* __restrict__ bias,
                                                  const float* __restrict__ Xt,
                                                  float* __restrict__ Y,
                                                  int M) {
    extern __shared__ float smf[];
    const int tid  = threadIdx.x;
    const int wid  = tid >> 5;
    const int lane = tid & 31;
    const int gid  = lane >> 2;
    const int tig  = lane & 3;
    const int K    = NC;
    const int n_blk = blockIdx.x << 7;
    const int m_blk = blockIdx.y << 7;
    const float* Xb = Xt + (size_t)blockIdx.z * NL * K;
    float*       Yb = Y  + (size_t)blockIdx.z * M * NL;
    const int wm = (wid >> 1) << 5;
    const int wn = (wid & 1) << 6;

    const int lrow = tid >> 3;
    const int lkg  = (tid & 7) << 2;
    const uint32_t sbase = smem_u32(smf);

    float acc[2][8][4];
    #pragma unroll
    for (int a = 0; a < 2; a++)
        #pragma unroll
        for (int b = 0; b < 8; b++)
            #pragma unroll
            for (int c = 0; c < 4; c++) acc[a][b][c] = 0.f;

    const int nkt = K / 32;
    {
        const float* wp = W  + (size_t)(m_blk + lrow) * K + lkg;
        const float* xp = Xb + (size_t)(n_blk + lrow) * K + lkg;
        #pragma unroll
        for (int i = 0; i < 4; i++) {
            uint32_t da = sbase + ((lrow + i * 32) * AST + lkg) * 4;
            uint32_t db = da + TILE_F * 4;
            CP_ASYNC16(da, wp + (size_t)i * 32 * K);
            CP_ASYNC16(db, xp + (size_t)i * 32 * K);
        }
        CP_COMMIT();
    }

    for (int kt = 0; kt < nkt; kt++) {
        const int bf = kt & 1;
        if (kt + 1 < nkt) {
            const int k0 = (kt + 1) << 5;
            const float* wp = W  + (size_t)(m_blk + lrow) * K + k0 + lkg;
            const float* xp = Xb + (size_t)(n_blk + lrow) * K + k0 + lkg;
            uint32_t base = sbase + (((kt + 1) & 1) ? 2 * TILE_F * 4 : 0);
            #pragma unroll
            for (int i = 0; i < 4; i++) {
                uint32_t da = base + ((lrow + i * 32) * AST + lkg) * 4;
                uint32_t db = da + TILE_F * 4;
                CP_ASYNC16(da, wp + (size_t)i * 32 * K);
                CP_ASYNC16(db, xp + (size_t)i * 32 * K);
            }
            CP_COMMIT();
            CP_WAIT(1);
        } else {
            CP_WAIT(0);
        }
        __syncthreads();

        const float* As = smf + (bf ? 2 * TILE_F : 0);
        const float* Bs = As + TILE_F;
        #pragma unroll
        for (int ks = 0; ks < 4; ks++) {
            const int k = ks << 3;
            uint32_t af[2][4];
            #pragma unroll
            for (int mt = 0; mt < 2; mt++) {
                int r0 = wm + (mt << 4) + gid;
                af[mt][0] = __float_as_uint(As[r0 * AST + k + tig]);
                af[mt][1] = __float_as_uint(As[(r0 + 8) * AST + k + tig]);
                af[mt][2] = __float_as_uint(As[r0 * AST + k + tig + 4]);
                af[mt][3] = __float_as_uint(As[(r0 + 8) * AST + k + tig + 4]);
            }
            #pragma unroll
            for (int nt = 0; nt < 8; nt++) {
                int n0 = wn + (nt << 3) + gid;
                uint32_t bfr[2];
                bfr[0] = __float_as_uint(Bs[n0 * AST + k + tig]);
                bfr[1] = __float_as_uint(Bs[n0 * AST + k + tig + 4]);
                mma_tf32(acc[0][nt], af[0], bfr);
                mma_tf32(acc[1][nt], af[1], bfr);
            }
        }
        __syncthreads();
    }

    #pragma unroll
    for (int mt = 0; mt < 2; mt++) {
        int m = m_blk + wm + (mt << 4) + gid;
        float bv0 = bias[m], bv1 = bias[m + 8];
        #pragma unroll
        for (int nt = 0; nt < 8; nt++) {
            int n = n_blk + wn + (nt << 3) + (tig << 1);
            float2 o0, o1;
            o0.x = acc[mt][nt][0] + bv0; o0.y = acc[mt][nt][1] + bv0;
            o1.x = acc[mt][nt][2] + bv1; o1.y = acc[mt][nt][3] + bv1;
            *(float2*)&Yb[(size_t)m * NL + n]       = o0;
            *(float2*)&Yb[(size_t)(m + 8) * NL + n] = o1;
        }
    }
}

// ---------------------------------------------------------------------------
// Flash attention with mma.sync tf32. grid = (8 t-tiles, 128 heads), 256 thr.
// K/V of the NEXT tile are LDG'd into registers right after the softmax sync
// and STS'd after the PV sync (latency hidden behind PV compute).
// ---------------------------------------------------------------------------
#define QST 136
#define VST 132
#define PST 132
#define ATTN_SMEM ((2 * 64 * QST + 64 * VST + 128 * PST + 3 * 128) * 4)

__global__ __launch_bounds__(256, 1) void attn_kernel() {
    extern __shared__ float sm[];
    float* Qs   = sm;                     // 64 x 136
    float* Ks   = Qs + 64 * QST;          // 64 x 136
    float* Vs   = Ks + 64 * QST;          // 64 x 132
    float* Ps   = Vs + 64 * VST;          // 128 x 132
    float* mrow = Ps + 128 * PST;
    float* lrow = mrow + 128;
    float* arow = lrow + 128;

    const int head = blockIdx.y;
    const int bi = head >> 3, hh = head & 7;
    const int t0 = blockIdx.x << 7;
    const float* qp = g_qkv + ((size_t)bi * NO3 + (size_t)hh * 192) * NL;
    const float* kp = qp + (size_t)64 * NL;
    const float* vp = kp + (size_t)64 * NL;
    const int tid  = threadIdx.x;
    const int wid  = tid >> 5;
    const int lane = tid & 31;
    const int gid  = lane >> 2;
    const int tig  = lane & 3;
    const int tb   = wid << 4;
    const int r0   = tb + gid, r1 = r0 + 8;

    const int lc   = tid >> 5;            // c row block base (8 per pass)
    const int lcol = (tid & 31) << 2;     // col within row

    // load Q (pre-scaled by 0.125), cvt once
    for (int v = tid; v < 2048; v += 256) {
        int c = v >> 5, col = (v & 31) << 2;
        float4 q = *(const float4*)&qp[(size_t)c * NL + t0 + col];
        uint4 o;
        o.x = cvt_tf32(q.x * 0.125f); o.y = cvt_tf32(q.y * 0.125f);
        o.z = cvt_tf32(q.z * 0.125f); o.w = cvt_tf32(q.w * 0.125f);
        *(uint4*)&Qs[c * QST + col] = o;
    }
    if (tid < 128) { mrow[tid] = -1e30f; lrow[tid] = 0.f; }
    // preload K/V tile 0
    #pragma unroll
    for (int i = 0; i < 8; i++) {
        int c = lc + i * 8;
        float4 kv = *(const float4*)&kp[(size_t)c * NL + lcol];
        float4 vv = *(const float4*)&vp[(size_t)c * NL + lcol];
        uint4 ok, ov;
        ok.x = cvt_tf32(kv.x); ok.y = cvt_tf32(kv.y);
        ok.z = cvt_tf32(kv.z); ok.w = cvt_tf32(kv.w);
        ov.x = cvt_tf32(vv.x); ov.y = cvt_tf32(vv.y);
        ov.z = cvt_tf32(vv.z); ov.w = cvt_tf32(vv.w);
        *(uint4*)&Ks[c * QST + lcol] = ok;
        *(uint4*)&Vs[c * VST + lcol] = ov;
    }

    float oacc[8][4];
    #pragma unroll
    for (int i = 0; i < 8; i++)
        #pragma unroll
        for (int j = 0; j < 4; j++) oacc[i][j] = 0.f;

    for (int s0 = 0; s0 < NL; s0 += 128) {
        __syncthreads();   // K/V (+P area free) ready

        // --- S = Q^T K
        float sacc[16][4];
        #pragma unroll
        for (int i = 0; i < 16; i++)
            #pragma unroll
            for (int j = 0; j < 4; j++) sacc[i][j] = 0.f;
        #pragma unroll
        for (int ks = 0; ks < 8; ks++) {
            const int k = ks << 3;
            uint32_t af[4];
            af[0] = __float_as_uint(Qs[(k + tig) * QST + tb + gid]);
            af[1] = __float_as_uint(Qs[(k + tig) * QST + tb + gid + 8]);
            af[2] = __float_as_uint(Qs[(k + tig + 4) * QST + tb + gid]);
            af[3] = __float_as_uint(Qs[(k + tig + 4) * QST + tb + gid + 8]);
            #pragma unroll
            for (int nt = 0; nt < 16; nt++) {
                int sc = (nt << 3) + gid;
                uint32_t bfr[2];
                bfr[0] = __float_as_uint(Ks[(k + tig) * QST + sc]);
                bfr[1] = __float_as_uint(Ks[(k + tig + 4) * QST + sc]);
                mma_tf32(sacc[nt], af, bfr);
            }
        }

        // --- online softmax
        float mx0 = -1e30f, mx1 = -1e30f;
        #pragma unroll
        for (int nt = 0; nt < 16; nt++) {
            mx0 = fmaxf(mx0, fmaxf(sacc[nt][0], sacc[nt][1]));
            mx1 = fmaxf(mx1, fmaxf(sacc[nt][2], sacc[nt][3]));
        }
        mx0 = fmaxf(mx0, __shfl_xor_sync(0xffffffffu, mx0, 1));
        mx0 = fmaxf(mx0, __shfl_xor_sync(0xffffffffu, mx0, 2));
        mx1 = fmaxf(mx1, __shfl_xor_sync(0xffffffffu, mx1, 1));
        mx1 = fmaxf(mx1, __shfl_xor_sync(0xffffffffu, mx1, 2));
        float mo0 = mrow[r0], mo1 = mrow[r1];
        float mn0 = fmaxf(mo0, mx0), mn1 = fmaxf(mo1, mx1);
        float sum0 = 0.f, sum1 = 0.f;
        #pragma unroll
        for (int nt = 0; nt < 16; nt++) {
            float p0 = fexp(sacc[nt][0] - mn0);
            float p1 = fexp(sacc[nt][1] - mn0);
            float p2 = fexp(sacc[nt][2] - mn1);
            float p3 = fexp(sacc[nt][3] - mn1);
            sum0 += p0 + p1; sum1 += p2 + p3;
            sacc[nt][0] = p0; sacc[nt][1] = p1;
            sacc[nt][2] = p2; sacc[nt][3] = p3;
        }
        sum0 += __shfl_xor_sync(0xffffffffu, sum0, 1);
        sum0 += __shfl_xor_sync(0xffffffffu, sum0, 2);
        sum1 += __shfl_xor_sync(0xffffffffu, sum1, 1);
        sum1 += __shfl_xor_sync(0xffffffffu, sum1, 2);
        if (tig == 0) {
            float al0 = fexp(mo0 - mn0), al1 = fexp(mo1 - mn1);
            lrow[r0] = lrow[r0] * al0 + sum0;
            lrow[r1] = lrow[r1] * al1 + sum1;
            mrow[r0] = mn0; mrow[r1] = mn1;
            arow[r0] = al0; arow[r1] = al1;
        }
        // write P (tf32, float2)
        #pragma unroll
        for (int nt = 0; nt < 16; nt++) {
            int c0 = (nt << 3) + (tig << 1);
            float2 w0, w1;
            w0.x = __uint_as_float(cvt_tf32(sacc[nt][0]));
            w0.y = __uint_as_float(cvt_tf32(sacc[nt][1]));
            w1.x = __uint_as_float(cvt_tf32(sacc[nt][2]));
            w1.y = __uint_as_float(cvt_tf32(sacc[nt][3]));
            *(float2*)&Ps[r0 * PST + c0] = w0;
            *(float2*)&Ps[r1 * PST + c0] = w1;
        }
        __syncthreads();   // P visible; Ks no longer read

        // --- prefetch next K/V into registers (hidden behind PV)
        const bool pf = (s0 + 128) < NL;
        float4 kreg[8], vreg[8];
        if (pf) {
            #pragma unroll
            for (int i = 0; i < 8; i++) {
                int c = lc + i * 8;
                kreg[i] = *(const float4*)&kp[(size_t)c * NL + s0 + 128 + lcol];
                vreg[i] = *(const float4*)&vp[(size_t)c * NL + s0 + 128 + lcol];
            }
        }

        // --- O = O*alpha + P V^T
        float al0 = arow[r0], al1 = arow[r1];
        #pragma unroll
        for (int nt = 0; nt < 8; nt++) {
            oacc[nt][0] *= al0; oacc[nt][1] *= al0;
            oacc[nt][2] *= al1; oacc[nt][3] *= al1;
        }
        #pragma unroll
        for (int ks = 0; ks < 16; ks++) {
            const int k = ks << 3;
            uint32_t af[4];
            af[0] = __float_as_uint(Ps[(tb + gid) * PST + k + tig]);
            af[1] = __float_as_uint(Ps[(tb + gid + 8) * PST + k + tig]);
            af[2] = __float_as_uint(Ps[(tb + gid) * PST + k + tig + 4]);
            af[3] = __float_as_uint(Ps[(tb + gid + 8) * PST + k + tig + 4]);
            #pragma unroll
            for (int nt = 0; nt < 8; nt++) {
                int cc = (nt << 3) + gid;
                uint32_t bfr[2];
                bfr[0] = __float_as_uint(Vs[cc * VST + k + tig]);
                bfr[1] = __float_as_uint(Vs[cc * VST + k + tig + 4]);
                mma_tf32(oacc[nt], af, bfr);
            }
        }
        __syncthreads();   // PV done reading Vs/Ps

        if (pf) {
            #pragma unroll
            for (int i = 0; i < 8; i++) {
                int c = lc + i * 8;
                uint4 ok, ov;
                ok.x = cvt_tf32(kreg[i].x); ok.y = cvt_tf32(kreg[i].y);
                ok.z = cvt_tf32(kreg[i].z); ok.w = cvt_tf32(kreg[i].w);
                ov.x = cvt_tf32(vreg[i].x); ov.y = cvt_tf32(vreg[i].y);
                ov.z = cvt_tf32(vreg[i].z); ov.w = cvt_tf32(vreg[i].w);
                *(uint4*)&Ks[c * QST + lcol] = ok;
                *(uint4*)&Vs[c * VST + lcol] = ov;
            }
        }
    }

    // epilogue: divide by l, write TRANSPOSED tf32 a_t[b][t0+t][hh*64 + c]
    __syncthreads();
    float inv0 = 1.0f / lrow[r0], inv1 = 1.0f / lrow[r1];
    float* op = g_at + ((size_t)bi * NL + t0) * NC + hh * 64;
    #pragma unroll
    for (int nt = 0; nt < 8; nt++) {
        int c0 = (nt << 3) + (tig << 1);
        float2 o0, o1;
        o0.x = cvt_tf32f(oacc[nt][0] * inv0); o0.y = cvt_tf32f(oacc[nt][1] * inv0);
        o1.x = cvt_tf32f(oacc[nt][2] * inv1); o1.y = cvt_tf32f(oacc[nt][3] * inv1);
        *(float2*)&op[(size_t)r0 * NC + c0] = o0;
        *(float2*)&op[(size_t)r1 * NC + c0] = o1;
    }
}

// ---------------------------------------------------------------------------
extern "C" void kernel_launch(void* const* d_in, const int* in_sizes, int n_in,
                              void* d_out, int out_size) {
    const float* x     = (const float*)d_in[0];
    const float* nw    = (const float*)d_in[1];
    const float* nb    = (const float*)d_in[2];
    const float* wqkv  = (const float*)d_in[3];
    const float* bqkv  = (const float*)d_in[4];
    const float* wproj = (const float*)d_in[5];
    const float* bproj = (const float*)d_in[6];
    float* out = (float*)d_out;

    float *pht, *pq, *pat, *pwt;
    cudaGetSymbolAddress((void**)&pht, g_ht);
    cudaGetSymbolAddress((void**)&pq,  g_qkv);
    cudaGetSymbolAddress((void**)&pat, g_at);
    cudaGetSymbolAddress((void**)&pwt, g_wt);

    cvt_w_kernel<<<768, 256>>>(wqkv,  pwt,                 NO3 * NC / 4);
    cvt_w_kernel<<<256, 256>>>(wproj, pwt + (size_t)NO3 * NC, NC * NC / 4);
    gn_kernel<<<512, 256>>>(x, nw, nb);

    cudaFuncSetAttribute(tc_gemm,
                         cudaFuncAttributeMaxDynamicSharedMemorySize, GEMM_SMEM);
    tc_gemm<<<dim3(8, 12, 16), 256, GEMM_SMEM>>>(pwt, bqkv, pht, pq, NO3);

    cudaFuncSetAttribute(attn_kernel,
                         cudaFuncAttributeMaxDynamicSharedMemorySize, ATTN_SMEM);
    attn_kernel<<<dim3(8, 128), 256, ATTN_SMEM>>>();

    tc_gemm<<<dim3(8, 4, 16), 256, GEMM_SMEM>>>(pwt + (size_t)NO3 * NC, bproj,
                                                pat, out, NC);
}

// round 7
// speedup vs baseline: 1.3556x; 1.3556x over previous
#include <cuda_runtime.h>
#include <cstdint>
#include <math.h>

// Problem constants: B=16, C=512, L=1024 (32x32), 32 groups, 8 heads, ch=64.
#define NB   16
#define NC   512
#define NL   1024
#define NO3  1536

// Scratch (device globals; no allocation allowed)
__device__ float g_ht [(size_t)NB * NL * NC];    // 32 MB groupnorm out, [b][l][c], tf32 bits
__device__ float g_qkv[(size_t)NB * NO3 * NL];   // 96 MB [b][o][l], fp32
__device__ float g_at [(size_t)NB * NL * NC];    // 32 MB attention out, [b][l][c], tf32 bits
__device__ float g_wt [(size_t)(NO3 + NC) * NC]; // 4 MB  weights, tf32 bits

// ===========================================================================
// helpers
// ===========================================================================
__device__ __forceinline__ uint32_t cvt_tf32(float x) {
    uint32_t r;
    asm("cvt.rna.tf32.f32 %0, %1;" : "=r"(r) : "f"(x));
    return r;
}
__device__ __forceinline__ float cvt_tf32f(float x) {
    return __uint_as_float(cvt_tf32(x));
}
__device__ __forceinline__ void mma_tf32(float* d, const uint32_t* a,
                                         const uint32_t* b) {
    asm volatile(
        "mma.sync.aligned.m16n8k8.row.col.f32.tf32.tf32.f32 "
        "{%0,%1,%2,%3}, {%4,%5,%6,%7}, {%8,%9}, {%0,%1,%2,%3};"
        : "+f"(d[0]), "+f"(d[1]), "+f"(d[2]), "+f"(d[3])
        : "r"(a[0]), "r"(a[1]), "r"(a[2]), "r"(a[3]), "r"(b[0]), "r"(b[1]));
}
#define CP_ASYNC16(dst, src) \
    asm volatile("cp.async.cg.shared.global [%0], [%1], 16;" \
                 :: "r"(dst), "l"(src) : "memory")
#define CP_COMMIT() asm volatile("cp.async.commit_group;" ::: "memory")
#define CP_WAIT(n)  asm volatile("cp.async.wait_group %0;" :: "n"(n) : "memory")

__device__ __forceinline__ uint32_t smem_u32(const void* p) {
    uint32_t a;
    asm("{ .reg .u64 t; cvta.to.shared.u64 t, %1; cvt.u32.u64 %0, t; }"
        : "=r"(a) : "l"(p));
    return a;
}

// fast exp on FMA pipe. x <= 0 expected.
__device__ __forceinline__ float fexp(float x) {
    float y = x * 1.4426950408889634f;
    y = fmaxf(y, -125.0f);
    int   e = __float2int_rd(y);
    float f = y - (float)e;
    float p = fmaf(0.0013333558f, f, 0.0096181291f);
    p = fmaf(p, f, 0.0555041087f);
    p = fmaf(p, f, 0.2402264758f);
    p = fmaf(p, f, 0.6931471806f);
    p = fmaf(p, f, 1.0f);
    return p * __int_as_float((e + 127) << 23);
}

// ---------------------------------------------------------------------------
// Pre-round weights to tf32 bits (grid-stride float4).
// ---------------------------------------------------------------------------
__global__ __launch_bounds__(256) void cvt_w_kernel(const float* __restrict__ src,
                                                    float* __restrict__ dst,
                                                    int n4) {
    int i = blockIdx.x * 256 + threadIdx.x;
    if (i < n4) {
        float4 v = ((const float4*)src)[i];
        v.x = cvt_tf32f(v.x); v.y = cvt_tf32f(v.y);
        v.z = cvt_tf32f(v.z); v.w = cvt_tf32f(v.w);
        ((float4*)dst)[i] = v;
    }
}

// ---------------------------------------------------------------------------
// GroupNorm: one block per (batch, group); writes TRANSPOSED h_t[b][l][c],
// tf32-rounded bits (GEMM consumes directly).
// ---------------------------------------------------------------------------
__global__ __launch_bounds__(256) void gn_kernel(const float* __restrict__ x,
                                                 const float* __restrict__ w,
                                                 const float* __restrict__ b) {
    const int blk = blockIdx.x;
    const int bi  = blk >> 5;
    const int g   = blk & 31;
    const float* xg = x + ((size_t)bi * NC + (size_t)g * 16) * NL;
    const int tid = threadIdx.x;

    float s = 0.f, s2 = 0.f;
    for (int v = tid; v < 4096; v += 256) {
        float4 q = *(const float4*)(xg + (size_t)v * 4);
        s  += q.x + q.y + q.z + q.w;
        s2 += q.x*q.x + q.y*q.y + q.z*q.z + q.w*q.w;
    }
    #pragma unroll
    for (int d = 16; d; d >>= 1) {
        s  += __shfl_xor_sync(0xffffffffu, s,  d);
        s2 += __shfl_xor_sync(0xffffffffu, s2, d);
    }
    __shared__ float rs[8], rs2[8];
    __shared__ float smean, srstd;
    if ((tid & 31) == 0) { rs[tid >> 5] = s; rs2[tid >> 5] = s2; }
    __syncthreads();
    if (tid == 0) {
        float ts = 0.f, ts2 = 0.f;
        #pragma unroll
        for (int i = 0; i < 8; i++) { ts += rs[i]; ts2 += rs2[i]; }
        float mean = ts * (1.0f / 16384.0f);
        float var  = ts2 * (1.0f / 16384.0f) - mean * mean;
        smean = mean;
        srstd = rsqrtf(var + 1e-5f);
    }
    __syncthreads();
    const float mean = smean, rstd = srstd;

    const float* xb = x + (size_t)bi * NC * NL;
    float* ob = g_ht + (size_t)bi * NL * NC;
    #pragma unroll
    for (int t = 0; t < 4; t++) {
        int idx = tid + t * 256;
        int l   = (idx & 255) << 2;
        int cb  = g * 16 + ((idx >> 8) << 2);
        float vin[4][4];
        float wc[4], bc[4];
        #pragma unroll
        for (int i = 0; i < 4; i++) {
            *(float4*)vin[i] = *(const float4*)&xb[(size_t)(cb + i) * NL + l];
            wc[i] = w[cb + i] * rstd;
            bc[i] = b[cb + i];
        }
        #pragma unroll
        for (int j = 0; j < 4; j++) {
            float4 o;
            o.x = cvt_tf32f((vin[0][j] - mean) * wc[0] + bc[0]);
            o.y = cvt_tf32f((vin[1][j] - mean) * wc[1] + bc[1]);
            o.z = cvt_tf32f((vin[2][j] - mean) * wc[2] + bc[2]);
            o.w = cvt_tf32f((vin[3][j] - mean) * wc[3] + bc[3]);
            *(float4*)&ob[(size_t)(l + j) * NC + cb] = o;
        }
    }
}

// ---------------------------------------------------------------------------
// mma.sync tf32 GEMM + bias. Inputs are already tf32-rounded bits.
// R3 config exactly (AST=40, 128x128 tile, BK=32, 8 warps, cp.async 2-stage),
// minus the per-fragment cvts.
// ---------------------------------------------------------------------------
#define AST 40
#define TILE_F (128 * AST)
#define GEMM_SMEM (4 * TILE_F * 4)            // 81920 B

__global__ __launch_bounds__(256, 2) void tc_gemm(const float* __restrict__ W,
                                                  const float* __restrict__ bias,
                                                  const float* __restrict__ Xt,
                                                  float* __restrict__ Y,
                                                  int M) {
    extern __shared__ float smf[];
    const int tid  = threadIdx.x;
    const int wid  = tid >> 5;
    const int lane = tid & 31;
    const int gid  = lane >> 2;
    const int tig  = lane & 3;
    const int K    = NC;
    const int n_blk = blockIdx.x << 7;
    const int m_blk = blockIdx.y << 7;
    const float* Xb = Xt + (size_t)blockIdx.z * NL * K;
    float*       Yb = Y  + (size_t)blockIdx.z * M * NL;
    const int wm = (wid >> 1) << 5;
    const int wn = (wid & 1) << 6;

    const int lrow = tid >> 3;
    const int lkg  = (tid & 7) << 2;
    const uint32_t sbase = smem_u32(smf);

    float acc[2][8][4];
    #pragma unroll
    for (int a = 0; a < 2; a++)
        #pragma unroll
        for (int b = 0; b < 8; b++)
            #pragma unroll
            for (int c = 0; c < 4; c++) acc[a][b][c] = 0.f;

    const int nkt = K / 32;
    {
        const float* wp = W  + (size_t)(m_blk + lrow) * K + lkg;
        const float* xp = Xb + (size_t)(n_blk + lrow) * K + lkg;
        #pragma unroll
        for (int i = 0; i < 4; i++) {
            uint32_t da = sbase + ((lrow + i * 32) * AST + lkg) * 4;
            uint32_t db = da + TILE_F * 4;
            CP_ASYNC16(da, wp + (size_t)i * 32 * K);
            CP_ASYNC16(db, xp + (size_t)i * 32 * K);
        }
        CP_COMMIT();
    }

    for (int kt = 0; kt < nkt; kt++) {
        const int bf = kt & 1;
        if (kt + 1 < nkt) {
            const int k0 = (kt + 1) << 5;
            const float* wp = W  + (size_t)(m_blk + lrow) * K + k0 + lkg;
            const float* xp = Xb + (size_t)(n_blk + lrow) * K + k0 + lkg;
            uint32_t base = sbase + (((kt + 1) & 1) ? 2 * TILE_F * 4 : 0);
            #pragma unroll
            for (int i = 0; i < 4; i++) {
                uint32_t da = base + ((lrow + i * 32) * AST + lkg) * 4;
                uint32_t db = da + TILE_F * 4;
                CP_ASYNC16(da, wp + (size_t)i * 32 * K);
                CP_ASYNC16(db, xp + (size_t)i * 32 * K);
            }
            CP_COMMIT();
            CP_WAIT(1);
        } else {
            CP_WAIT(0);
        }
        __syncthreads();

        const float* As = smf + (bf ? 2 * TILE_F : 0);
        const float* Bs = As + TILE_F;
        #pragma unroll
        for (int ks = 0; ks < 4; ks++) {
            const int k = ks << 3;
            uint32_t af[2][4];
            #pragma unroll
            for (int mt = 0; mt < 2; mt++) {
                int r0 = wm + (mt << 4) + gid;
                af[mt][0] = __float_as_uint(As[r0 * AST + k + tig]);
                af[mt][1] = __float_as_uint(As[(r0 + 8) * AST + k + tig]);
                af[mt][2] = __float_as_uint(As[r0 * AST + k + tig + 4]);
                af[mt][3] = __float_as_uint(As[(r0 + 8) * AST + k + tig + 4]);
            }
            #pragma unroll
            for (int nt = 0; nt < 8; nt++) {
                int n0 = wn + (nt << 3) + gid;
                uint32_t bfr[2];
                bfr[0] = __float_as_uint(Bs[n0 * AST + k + tig]);
                bfr[1] = __float_as_uint(Bs[n0 * AST + k + tig + 4]);
                mma_tf32(acc[0][nt], af[0], bfr);
                mma_tf32(acc[1][nt], af[1], bfr);
            }
        }
        __syncthreads();
    }

    #pragma unroll
    for (int mt = 0; mt < 2; mt++) {
        int m = m_blk + wm + (mt << 4) + gid;
        float bv0 = bias[m], bv1 = bias[m + 8];
        #pragma unroll
        for (int nt = 0; nt < 8; nt++) {
            int n = n_blk + wn + (nt << 3) + (tig << 1);
            float2 o0, o1;
            o0.x = acc[mt][nt][0] + bv0; o0.y = acc[mt][nt][1] + bv0;
            o1.x = acc[mt][nt][2] + bv1; o1.y = acc[mt][nt][3] + bv1;
            *(float2*)&Yb[(size_t)m * NL + n]       = o0;
            *(float2*)&Yb[(size_t)(m + 8) * NL + n] = o1;
        }
    }
}

// ---------------------------------------------------------------------------
// Flash attention with mma.sync tf32. grid = (8 t-tiles, 128 heads), 256 thr.
// V loaded (blocking) at loop top; K of the NEXT tile prefetched into 32
// registers after the P-sync and stored after the PV-sync.
// ---------------------------------------------------------------------------
#define QST 136
#define VST 132
#define PST 132
#define ATTN_SMEM ((2 * 64 * QST + 64 * VST + 128 * PST + 3 * 128) * 4)

__global__ __launch_bounds__(256, 1) void attn_kernel() {
    extern __shared__ float sm[];
    float* Qs   = sm;                     // 64 x 136
    float* Ks   = Qs + 64 * QST;          // 64 x 136
    float* Vs   = Ks + 64 * QST;          // 64 x 132
    float* Ps   = Vs + 64 * VST;          // 128 x 132
    float* mrow = Ps + 128 * PST;
    float* lrow = mrow + 128;
    float* arow = lrow + 128;

    const int head = blockIdx.y;
    const int bi = head >> 3, hh = head & 7;
    const int t0 = blockIdx.x << 7;
    const float* qp = g_qkv + ((size_t)bi * NO3 + (size_t)hh * 192) * NL;
    const float* kp = qp + (size_t)64 * NL;
    const float* vp = kp + (size_t)64 * NL;
    const int tid  = threadIdx.x;
    const int wid  = tid >> 5;
    const int lane = tid & 31;
    const int gid  = lane >> 2;
    const int tig  = lane & 3;
    const int tb   = wid << 4;
    const int r0   = tb + gid, r1 = r0 + 8;

    const int lc   = tid >> 5;            // c row base (8 rows per pass)
    const int lcol = (tid & 31) << 2;     // col within row

    // load Q (pre-scaled by 0.125), cvt once
    for (int v = tid; v < 2048; v += 256) {
        int c = v >> 5, col = (v & 31) << 2;
        float4 q = *(const float4*)&qp[(size_t)c * NL + t0 + col];
        uint4 o;
        o.x = cvt_tf32(q.x * 0.125f); o.y = cvt_tf32(q.y * 0.125f);
        o.z = cvt_tf32(q.z * 0.125f); o.w = cvt_tf32(q.w * 0.125f);
        *(uint4*)&Qs[c * QST + col] = o;
    }
    if (tid < 128) { mrow[tid] = -1e30f; lrow[tid] = 0.f; }
    // preload K tile 0
    #pragma unroll
    for (int i = 0; i < 8; i++) {
        int c = lc + i * 8;
        float4 kv = *(const float4*)&kp[(size_t)c * NL + lcol];
        uint4 ok;
        ok.x = cvt_tf32(kv.x); ok.y = cvt_tf32(kv.y);
        ok.z = cvt_tf32(kv.z); ok.w = cvt_tf32(kv.w);
        *(uint4*)&Ks[c * QST + lcol] = ok;
    }

    float oacc[8][4];
    #pragma unroll
    for (int i = 0; i < 8; i++)
        #pragma unroll
        for (int j = 0; j < 4; j++) oacc[i][j] = 0.f;

    for (int s0 = 0; s0 < NL; s0 += 128) {
        // load V(cur) blocking (Vs free: prev PV finished before trailing sync)
        #pragma unroll
        for (int i = 0; i < 8; i++) {
            int c = lc + i * 8;
            float4 vv = *(const float4*)&vp[(size_t)c * NL + s0 + lcol];
            uint4 ov;
            ov.x = cvt_tf32(vv.x); ov.y = cvt_tf32(vv.y);
            ov.z = cvt_tf32(vv.z); ov.w = cvt_tf32(vv.w);
            *(uint4*)&Vs[c * VST + lcol] = ov;
        }
        __syncthreads();   // Ks (prev-iter STS) + Vs visible

        // --- S = Q^T K
        float sacc[16][4];
        #pragma unroll
        for (int i = 0; i < 16; i++)
            #pragma unroll
            for (int j = 0; j < 4; j++) sacc[i][j] = 0.f;
        #pragma unroll
        for (int ks = 0; ks < 8; ks++) {
            const int k = ks << 3;
            uint32_t af[4];
            af[0] = __float_as_uint(Qs[(k + tig) * QST + tb + gid]);
            af[1] = __float_as_uint(Qs[(k + tig) * QST + tb + gid + 8]);
            af[2] = __float_as_uint(Qs[(k + tig + 4) * QST + tb + gid]);
            af[3] = __float_as_uint(Qs[(k + tig + 4) * QST + tb + gid + 8]);
            #pragma unroll
            for (int nt = 0; nt < 16; nt++) {
                int sc = (nt << 3) + gid;
                uint32_t bfr[2];
                bfr[0] = __float_as_uint(Ks[(k + tig) * QST + sc]);
                bfr[1] = __float_as_uint(Ks[(k + tig + 4) * QST + sc]);
                mma_tf32(sacc[nt], af, bfr);
            }
        }

        // --- online softmax
        float mx0 = -1e30f, mx1 = -1e30f;
        #pragma unroll
        for (int nt = 0; nt < 16; nt++) {
            mx0 = fmaxf(mx0, fmaxf(sacc[nt][0], sacc[nt][1]));
            mx1 = fmaxf(mx1, fmaxf(sacc[nt][2], sacc[nt][3]));
        }
        mx0 = fmaxf(mx0, __shfl_xor_sync(0xffffffffu, mx0, 1));
        mx0 = fmaxf(mx0, __shfl_xor_sync(0xffffffffu, mx0, 2));
        mx1 = fmaxf(mx1, __shfl_xor_sync(0xffffffffu, mx1, 1));
        mx1 = fmaxf(mx1, __shfl_xor_sync(0xffffffffu, mx1, 2));
        float mo0 = mrow[r0], mo1 = mrow[r1];
        float mn0 = fmaxf(mo0, mx0), mn1 = fmaxf(mo1, mx1);
        float sum0 = 0.f, sum1 = 0.f;
        #pragma unroll
        for (int nt = 0; nt < 16; nt++) {
            float p0 = fexp(sacc[nt][0] - mn0);
            float p1 = fexp(sacc[nt][1] - mn0);
            float p2 = fexp(sacc[nt][2] - mn1);
            float p3 = fexp(sacc[nt][3] - mn1);
            sum0 += p0 + p1; sum1 += p2 + p3;
            sacc[nt][0] = p0; sacc[nt][1] = p1;
            sacc[nt][2] = p2; sacc[nt][3] = p3;
        }
        sum0 += __shfl_xor_sync(0xffffffffu, sum0, 1);
        sum0 += __shfl_xor_sync(0xffffffffu, sum0, 2);
        sum1 += __shfl_xor_sync(0xffffffffu, sum1, 1);
        sum1 += __shfl_xor_sync(0xffffffffu, sum1, 2);
        if (tig == 0) {
            float al0 = fexp(mo0 - mn0), al1 = fexp(mo1 - mn1);
            lrow[r0] = lrow[r0] * al0 + sum0;
            lrow[r1] = lrow[r1] * al1 + sum1;
            mrow[r0] = mn0; mrow[r1] = mn1;
            arow[r0] = al0; arow[r1] = al1;
        }
        // write P (tf32, float2)
        #pragma unroll
        for (int nt = 0; nt < 16; nt++) {
            int c0 = (nt << 3) + (tig << 1);
            float2 w0, w1;
            w0.x = __uint_as_float(cvt_tf32(sacc[nt][0]));
            w0.y = __uint_as_float(cvt_tf32(sacc[nt][1]));
            w1.x = __uint_as_float(cvt_tf32(sacc[nt][2]));
            w1.y = __uint_as_float(cvt_tf32(sacc[nt][3]));
            *(float2*)&Ps[r0 * PST + c0] = w0;
            *(float2*)&Ps[r1 * PST + c0] = w1;
        }
        __syncthreads();   // P visible; Ks no longer read

        // --- prefetch next K into registers only (32 regs)
        const bool pf = (s0 + 128) < NL;
        float4 kreg[8];
        if (pf) {
            #pragma unroll
            for (int i = 0; i < 8; i++) {
                int c = lc + i * 8;
                kreg[i] = *(const float4*)&kp[(size_t)c * NL + s0 + 128 + lcol];
            }
        }

        // --- O = O*alpha + P V^T
        float al0 = arow[r0], al1 = arow[r1];
        #pragma unroll
        for (int nt = 0; nt < 8; nt++) {
            oacc[nt][0] *= al0; oacc[nt][1] *= al0;
            oacc[nt][2] *= al1; oacc[nt][3] *= al1;
        }
        #pragma unroll
        for (int ks = 0; ks < 16; ks++) {
            const int k = ks << 3;
            uint32_t af[4];
            af[0] = __float_as_uint(Ps[(tb + gid) * PST + k + tig]);
            af[1] = __float_as_uint(Ps[(tb + gid + 8) * PST + k + tig]);
            af[2] = __float_as_uint(Ps[(tb + gid) * PST + k + tig + 4]);
            af[3] = __float_as_uint(Ps[(tb + gid + 8) * PST + k + tig + 4]);
            #pragma unroll
            for (int nt = 0; nt < 8; nt++) {
                int cc = (nt << 3) + gid;
                uint32_t bfr[2];
                bfr[0] = __float_as_uint(Vs[cc * VST + k + tig]);
                bfr[1] = __float_as_uint(Vs[cc * VST + k + tig + 4]);
                mma_tf32(oacc[nt], af, bfr);
            }
        }
        __syncthreads();   // PV done reading Vs/Ps; Ks writable

        if (pf) {
            #pragma unroll
            for (int i = 0; i < 8; i++) {
                int c = lc + i * 8;
                uint4 ok;
                ok.x = cvt_tf32(kreg[i].x); ok.y = cvt_tf32(kreg[i].y);
                ok.z = cvt_tf32(kreg[i].z); ok.w = cvt_tf32(kreg[i].w);
                *(uint4*)&Ks[c * QST + lcol] = ok;
            }
        }
    }

    // epilogue: divide by l, write TRANSPOSED tf32 a_t[b][t0+t][hh*64 + c]
    __syncthreads();
    float inv0 = 1.0f / lrow[r0], inv1 = 1.0f / lrow[r1];
    float* op = g_at + ((size_t)bi * NL + t0) * NC + hh * 64;
    #pragma unroll
    for (int nt = 0; nt < 8; nt++) {
        int c0 = (nt << 3) + (tig << 1);
        float2 o0, o1;
        o0.x = cvt_tf32f(oacc[nt][0] * inv0); o0.y = cvt_tf32f(oacc[nt][1] * inv0);
        o1.x = cvt_tf32f(oacc[nt][2] * inv1); o1.y = cvt_tf32f(oacc[nt][3] * inv1);
        *(float2*)&op[(size_t)r0 * NC + c0] = o0;
        *(float2*)&op[(size_t)r1 * NC + c0] = o1;
    }
}

// ---------------------------------------------------------------------------
extern "C" void kernel_launch(void* const* d_in, const int* in_sizes, int n_in,
                              void* d_out, int out_size) {
    const float* x     = (const float*)d_in[0];
    const float* nw    = (const float*)d_in[1];
    const float* nb    = (const float*)d_in[2];
    const float* wqkv  = (const float*)d_in[3];
    const float* bqkv  = (const float*)d_in[4];
    const float* wproj = (const float*)d_in[5];
    const float* bproj = (const float*)d_in[6];
    float* out = (float*)d_out;

    float *pht, *pq, *pat, *pwt;
    cudaGetSymbolAddress((void**)&pht, g_ht);
    cudaGetSymbolAddress((void**)&pq,  g_qkv);
    cudaGetSymbolAddress((void**)&pat, g_at);
    cudaGetSymbolAddress((void**)&pwt, g_wt);

    cvt_w_kernel<<<768, 256>>>(wqkv,  pwt,                    NO3 * NC / 4);
    cvt_w_kernel<<<256, 256>>>(wproj, pwt + (size_t)NO3 * NC, NC * NC / 4);
    gn_kernel<<<512, 256>>>(x, nw, nb);

    cudaFuncSetAttribute(tc_gemm,
                         cudaFuncAttributeMaxDynamicSharedMemorySize, GEMM_SMEM);
    tc_gemm<<<dim3(8, 12, 16), 256, GEMM_SMEM>>>(pwt, bqkv, pht, pq, NO3);

    cudaFuncSetAttribute(attn_kernel,
                         cudaFuncAttributeMaxDynamicSharedMemorySize, ATTN_SMEM);
    attn_kernel<<<dim3(8, 128), 256, ATTN_SMEM>>>();

    tc_gemm<<<dim3(8, 4, 16), 256, GEMM_SMEM>>>(pwt + (size_t)NO3 * NC, bproj,
                                                pat, out, NC);
}

// round 9
// speedup vs baseline: 1.4520x; 1.0711x over previous
#include <cuda_runtime.h>
#include <cstdint>
#include <math.h>

// Problem constants: B=16, C=512, L=1024 (32x32), 32 groups, 8 heads, ch=64.
#define NB   16
#define NC   512
#define NL   1024
#define NO3  1536

// Scratch (device globals; no allocation allowed)
__device__ float g_ht [(size_t)NB * NL * NC];    // 32 MB groupnorm out, [b][l][c], tf32 bits
__device__ float g_qkv[(size_t)NB * NO3 * NL];   // 96 MB [b][o][l], fp32
__device__ float g_at [(size_t)NB * NL * NC];    // 32 MB attention out, [b][l][c], tf32 bits
__device__ float g_wt [(size_t)(NO3 + NC) * NC]; // 4 MB  weights, tf32 bits

// ===========================================================================
// helpers
// ===========================================================================
__device__ __forceinline__ uint32_t cvt_tf32(float x) {
    uint32_t r;
    asm("cvt.rna.tf32.f32 %0, %1;" : "=r"(r) : "f"(x));
    return r;
}
__device__ __forceinline__ float cvt_tf32f(float x) {
    return __uint_as_float(cvt_tf32(x));
}
__device__ __forceinline__ void mma_tf32(float* d, const uint32_t* a,
                                         const uint32_t* b) {
    asm volatile(
        "mma.sync.aligned.m16n8k8.row.col.f32.tf32.tf32.f32 "
        "{%0,%1,%2,%3}, {%4,%5,%6,%7}, {%8,%9}, {%0,%1,%2,%3};"
        : "+f"(d[0]), "+f"(d[1]), "+f"(d[2]), "+f"(d[3])
        : "r"(a[0]), "r"(a[1]), "r"(a[2]), "r"(a[3]), "r"(b[0]), "r"(b[1]));
}
#define CP_ASYNC16(dst, src) \
    asm volatile("cp.async.cg.shared.global [%0], [%1], 16;" \
                 :: "r"(dst), "l"(src) : "memory")
#define CP_COMMIT() asm volatile("cp.async.commit_group;" ::: "memory")
#define CP_WAIT(n)  asm volatile("cp.async.wait_group %0;" :: "n"(n) : "memory")

__device__ __forceinline__ uint32_t smem_u32(const void* p) {
    uint32_t a;
    asm("{ .reg .u64 t; cvta.to.shared.u64 t, %1; cvt.u32.u64 %0, t; }"
        : "=r"(a) : "l"(p));
    return a;
}

// fast exp on FMA pipe. x <= 0 expected.
__device__ __forceinline__ float fexp(float x) {
    float y = x * 1.4426950408889634f;
    y = fmaxf(y, -125.0f);
    int   e = __float2int_rd(y);
    float f = y - (float)e;
    float p = fmaf(0.0013333558f, f, 0.0096181291f);
    p = fmaf(p, f, 0.0555041087f);
    p = fmaf(p, f, 0.2402264758f);
    p = fmaf(p, f, 0.6931471806f);
    p = fmaf(p, f, 1.0f);
    return p * __int_as_float((e + 127) << 23);
}

// ---------------------------------------------------------------------------
// Pre-round weights to tf32 bits (grid-stride float4).
// ---------------------------------------------------------------------------
__global__ __launch_bounds__(256) void cvt_w_kernel(const float* __restrict__ src,
                                                    float* __restrict__ dst,
                                                    int n4) {
    int i = blockIdx.x * 256 + threadIdx.x;
    if (i < n4) {
        float4 v = ((const float4*)src)[i];
        v.x = cvt_tf32f(v.x); v.y = cvt_tf32f(v.y);
        v.z = cvt_tf32f(v.z); v.w = cvt_tf32f(v.w);
        ((float4*)dst)[i] = v;
    }
}

// ---------------------------------------------------------------------------
// GroupNorm: one block per (batch, group); writes TRANSPOSED h_t[b][l][c],
// tf32-rounded bits (GEMM consumes directly).
// ---------------------------------------------------------------------------
__global__ __launch_bounds__(256) void gn_kernel(const float* __restrict__ x,
                                                 const float* __restrict__ w,
                                                 const float* __restrict__ b) {
    const int blk = blockIdx.x;
    const int bi  = blk >> 5;
    const int g   = blk & 31;
    const float* xg = x + ((size_t)bi * NC + (size_t)g * 16) * NL;
    const int tid = threadIdx.x;

    float s = 0.f, s2 = 0.f;
    for (int v = tid; v < 4096; v += 256) {
        float4 q = *(const float4*)(xg + (size_t)v * 4);
        s  += q.x + q.y + q.z + q.w;
        s2 += q.x*q.x + q.y*q.y + q.z*q.z + q.w*q.w;
    }
    #pragma unroll
    for (int d = 16; d; d >>= 1) {
        s  += __shfl_xor_sync(0xffffffffu, s,  d);
        s2 += __shfl_xor_sync(0xffffffffu, s2, d);
    }
    __shared__ float rs[8], rs2[8];
    __shared__ float smean, srstd;
    if ((tid & 31) == 0) { rs[tid >> 5] = s; rs2[tid >> 5] = s2; }
    __syncthreads();
    if (tid == 0) {
        float ts = 0.f, ts2 = 0.f;
        #pragma unroll
        for (int i = 0; i < 8; i++) { ts += rs[i]; ts2 += rs2[i]; }
        float mean = ts * (1.0f / 16384.0f);
        float var  = ts2 * (1.0f / 16384.0f) - mean * mean;
        smean = mean;
        srstd = rsqrtf(var + 1e-5f);
    }
    __syncthreads();
    const float mean = smean, rstd = srstd;

    const float* xb = x + (size_t)bi * NC * NL;
    float* ob = g_ht + (size_t)bi * NL * NC;
    #pragma unroll
    for (int t = 0; t < 4; t++) {
        int idx = tid + t * 256;
        int l   = (idx & 255) << 2;
        int cb  = g * 16 + ((idx >> 8) << 2);
        float vin[4][4];
        float wc[4], bc[4];
        #pragma unroll
        for (int i = 0; i < 4; i++) {
            *(float4*)vin[i] = *(const float4*)&xb[(size_t)(cb + i) * NL + l];
            wc[i] = w[cb + i] * rstd;
            bc[i] = b[cb + i];
        }
        #pragma unroll
        for (int j = 0; j < 4; j++) {
            float4 o;
            o.x = cvt_tf32f((vin[0][j] - mean) * wc[0] + bc[0]);
            o.y = cvt_tf32f((vin[1][j] - mean) * wc[1] + bc[1]);
            o.z = cvt_tf32f((vin[2][j] - mean) * wc[2] + bc[2]);
            o.w = cvt_tf32f((vin[3][j] - mean) * wc[3] + bc[3]);
            *(float4*)&ob[(size_t)(l + j) * NC + cb] = o;
        }
    }
}

// ---------------------------------------------------------------------------
// mma.sync tf32 GEMM + bias. (unchanged from R7)
// ---------------------------------------------------------------------------
#define AST 40
#define TILE_F (128 * AST)
#define GEMM_SMEM (4 * TILE_F * 4)            // 81920 B

__global__ __launch_bounds__(256, 2) void tc_gemm(const float* __restrict__ W,
                                                  const float* __restrict__ bias,
                                                  const float* __restrict__ Xt,
                                                  float* __restrict__ Y,
                                                  int M) {
    extern __shared__ float smf[];
    const int tid  = threadIdx.x;
    const int wid  = tid >> 5;
    const int lane = tid & 31;
    const int gid  = lane >> 2;
    const int tig  = lane & 3;
    const int K    = NC;
    const int n_blk = blockIdx.x << 7;
    const int m_blk = blockIdx.y << 7;
    const float* Xb = Xt + (size_t)blockIdx.z * NL * K;
    float*       Yb = Y  + (size_t)blockIdx.z * M * NL;
    const int wm = (wid >> 1) << 5;
    const int wn = (wid & 1) << 6;

    const int lrow = tid >> 3;
    const int lkg  = (tid & 7) << 2;
    const uint32_t sbase = smem_u32(smf);

    float acc[2][8][4];
    #pragma unroll
    for (int a = 0; a < 2; a++)
        #pragma unroll
        for (int b = 0; b < 8; b++)
            #pragma unroll
            for (int c = 0; c < 4; c++) acc[a][b][c] = 0.f;

    const int nkt = K / 32;
    {
        const float* wp = W  + (size_t)(m_blk + lrow) * K + lkg;
        const float* xp = Xb + (size_t)(n_blk + lrow) * K + lkg;
        #pragma unroll
        for (int i = 0; i < 4; i++) {
            uint32_t da = sbase + ((lrow + i * 32) * AST + lkg) * 4;
            uint32_t db = da + TILE_F * 4;
            CP_ASYNC16(da, wp + (size_t)i * 32 * K);
            CP_ASYNC16(db, xp + (size_t)i * 32 * K);
        }
        CP_COMMIT();
    }

    for (int kt = 0; kt < nkt; kt++) {
        const int bf = kt & 1;
        if (kt + 1 < nkt) {
            const int k0 = (kt + 1) << 5;
            const float* wp = W  + (size_t)(m_blk + lrow) * K + k0 + lkg;
            const float* xp = Xb + (size_t)(n_blk + lrow) * K + k0 + lkg;
            uint32_t base = sbase + (((kt + 1) & 1) ? 2 * TILE_F * 4 : 0);
            #pragma unroll
            for (int i = 0; i < 4; i++) {
                uint32_t da = base + ((lrow + i * 32) * AST + lkg) * 4;
                uint32_t db = da + TILE_F * 4;
                CP_ASYNC16(da, wp + (size_t)i * 32 * K);
                CP_ASYNC16(db, xp + (size_t)i * 32 * K);
            }
            CP_COMMIT();
            CP_WAIT(1);
        } else {
            CP_WAIT(0);
        }
        __syncthreads();

        const float* As = smf + (bf ? 2 * TILE_F : 0);
        const float* Bs = As + TILE_F;
        #pragma unroll
        for (int ks = 0; ks < 4; ks++) {
            const int k = ks << 3;
            uint32_t af[2][4];
            #pragma unroll
            for (int mt = 0; mt < 2; mt++) {
                int r0 = wm + (mt << 4) + gid;
                af[mt][0] = __float_as_uint(As[r0 * AST + k + tig]);
                af[mt][1] = __float_as_uint(As[(r0 + 8) * AST + k + tig]);
                af[mt][2] = __float_as_uint(As[r0 * AST + k + tig + 4]);
                af[mt][3] = __float_as_uint(As[(r0 + 8) * AST + k + tig + 4]);
            }
            #pragma unroll
            for (int nt = 0; nt < 8; nt++) {
                int n0 = wn + (nt << 3) + gid;
                uint32_t bfr[2];
                bfr[0] = __float_as_uint(Bs[n0 * AST + k + tig]);
                bfr[1] = __float_as_uint(Bs[n0 * AST + k + tig + 4]);
                mma_tf32(acc[0][nt], af[0], bfr);
                mma_tf32(acc[1][nt], af[1], bfr);
            }
        }
        __syncthreads();
    }

    #pragma unroll
    for (int mt = 0; mt < 2; mt++) {
        int m = m_blk + wm + (mt << 4) + gid;
        float bv0 = bias[m], bv1 = bias[m + 8];
        #pragma unroll
        for (int nt = 0; nt < 8; nt++) {
            int n = n_blk + wn + (nt << 3) + (tig << 1);
            float2 o0, o1;
            o0.x = acc[mt][nt][0] + bv0; o0.y = acc[mt][nt][1] + bv0;
            o1.x = acc[mt][nt][2] + bv1; o1.y = acc[mt][nt][3] + bv1;
            *(float2*)&Yb[(size_t)m * NL + n]       = o0;
            *(float2*)&Yb[(size_t)(m + 8) * NL + n] = o1;
        }
    }
}

// ---------------------------------------------------------------------------
// Flash attention, mma.sync tf32, REGISTER-P version.
// grid = (8 t-tiles, 128 heads), 256 threads (8 warps, warp owns 16 t-rows).
// - P never touches smem: QK C-fragments are remapped to PV A-fragments with
//   intra-warp shuffles (8 shfl per k-step).
// - Softmax row state (m, l) lives in registers (per warp/gid, all 4 tig
//   lanes hold identical reduced values).
// smem = Q(64x136) + K(64x136) + V(64x132) = 103,424 B  ->  2 CTAs/SM.
// ---------------------------------------------------------------------------
#define QST 136
#define VST 132
#define ATTN_SMEM ((2 * 64 * QST + 64 * VST) * 4)

__global__ __launch_bounds__(256, 2) void attn_kernel() {
    extern __shared__ float sm[];
    float* Qs = sm;                     // 64 x 136  [c][t]
    float* Ks = Qs + 64 * QST;          // 64 x 136  [c][s]
    float* Vs = Ks + 64 * QST;          // 64 x 132  [c][s]

    const int head = blockIdx.y;
    const int bi = head >> 3, hh = head & 7;
    const int t0 = blockIdx.x << 7;
    const float* qp = g_qkv + ((size_t)bi * NO3 + (size_t)hh * 192) * NL;
    const float* kp = qp + (size_t)64 * NL;
    const float* vp = kp + (size_t)64 * NL;
    const int tid  = threadIdx.x;
    const int wid  = tid >> 5;
    const int lane = tid & 31;
    const int gid  = lane >> 2;
    const int tig  = lane & 3;
    const int tb   = wid << 4;
    const int r0   = tb + gid, r1 = r0 + 8;

    const int lc   = tid >> 5;            // c row base (8 rows per pass)
    const int lcol = (tid & 31) << 2;     // col within row

    // shuffle source lanes for C-frag -> A-frag remap
    const int Lsrc = (lane & 0x1c) | (tig >> 1);   // 4*gid + tig/2
    const bool hi  = (tig & 1);

    // load Q (pre-scaled by 0.125), cvt once
    for (int v = tid; v < 2048; v += 256) {
        int c = v >> 5, col = (v & 31) << 2;
        float4 q = *(const float4*)&qp[(size_t)c * NL + t0 + col];
        uint4 o;
        o.x = cvt_tf32(q.x * 0.125f); o.y = cvt_tf32(q.y * 0.125f);
        o.z = cvt_tf32(q.z * 0.125f); o.w = cvt_tf32(q.w * 0.125f);
        *(uint4*)&Qs[c * QST + col] = o;
    }
    // preload K/V tile 0
    #pragma unroll
    for (int i = 0; i < 8; i++) {
        int c = lc + i * 8;
        float4 kv = *(const float4*)&kp[(size_t)c * NL + lcol];
        float4 vv = *(const float4*)&vp[(size_t)c * NL + lcol];
        uint4 ok, ov;
        ok.x = cvt_tf32(kv.x); ok.y = cvt_tf32(kv.y);
        ok.z = cvt_tf32(kv.z); ok.w = cvt_tf32(kv.w);
        ov.x = cvt_tf32(vv.x); ov.y = cvt_tf32(vv.y);
        ov.z = cvt_tf32(vv.z); ov.w = cvt_tf32(vv.w);
        *(uint4*)&Ks[c * QST + lcol] = ok;
        *(uint4*)&Vs[c * VST + lcol] = ov;
    }

    float m0 = -1e30f, m1 = -1e30f, l0 = 0.f, l1 = 0.f;
    float oacc[8][4];
    #pragma unroll
    for (int i = 0; i < 8; i++)
        #pragma unroll
        for (int j = 0; j < 4; j++) oacc[i][j] = 0.f;

    for (int s0 = 0; s0 < NL; s0 += 128) {
        __syncthreads();   // K/V tile visible

        // --- S = Q^T K  (sacc[nt] covers s-cols [8nt, 8nt+8))
        float sacc[16][4];
        #pragma unroll
        for (int i = 0; i < 16; i++)
            #pragma unroll
            for (int j = 0; j < 4; j++) sacc[i][j] = 0.f;
        #pragma unroll
        for (int ks = 0; ks < 8; ks++) {
            const int k = ks << 3;
            uint32_t af[4];
            af[0] = __float_as_uint(Qs[(k + tig) * QST + tb + gid]);
            af[1] = __float_as_uint(Qs[(k + tig) * QST + tb + gid + 8]);
            af[2] = __float_as_uint(Qs[(k + tig + 4) * QST + tb + gid]);
            af[3] = __float_as_uint(Qs[(k + tig + 4) * QST + tb + gid + 8]);
            #pragma unroll
            for (int nt = 0; nt < 16; nt++) {
                int sc = (nt << 3) + gid;
                uint32_t bfr[2];
                bfr[0] = __float_as_uint(Ks[(k + tig) * QST + sc]);
                bfr[1] = __float_as_uint(Ks[(k + tig + 4) * QST + sc]);
                mma_tf32(sacc[nt], af, bfr);
            }
        }

        // --- online softmax (row state in registers)
        float mx0 = -1e30f, mx1 = -1e30f;
        #pragma unroll
        for (int nt = 0; nt < 16; nt++) {
            mx0 = fmaxf(mx0, fmaxf(sacc[nt][0], sacc[nt][1]));
            mx1 = fmaxf(mx1, fmaxf(sacc[nt][2], sacc[nt][3]));
        }
        mx0 = fmaxf(mx0, __shfl_xor_sync(0xffffffffu, mx0, 1));
        mx0 = fmaxf(mx0, __shfl_xor_sync(0xffffffffu, mx0, 2));
        mx1 = fmaxf(mx1, __shfl_xor_sync(0xffffffffu, mx1, 1));
        mx1 = fmaxf(mx1, __shfl_xor_sync(0xffffffffu, mx1, 2));
        float mn0 = fmaxf(m0, mx0), mn1 = fmaxf(m1, mx1);
        float sum0 = 0.f, sum1 = 0.f;
        #pragma unroll
        for (int nt = 0; nt < 16; nt++) {
            float p0 = fexp(sacc[nt][0] - mn0);
            float p1 = fexp(sacc[nt][1] - mn0);
            float p2 = fexp(sacc[nt][2] - mn1);
            float p3 = fexp(sacc[nt][3] - mn1);
            sum0 += p0 + p1; sum1 += p2 + p3;
            sacc[nt][0] = p0; sacc[nt][1] = p1;
            sacc[nt][2] = p2; sacc[nt][3] = p3;
        }
        sum0 += __shfl_xor_sync(0xffffffffu, sum0, 1);
        sum0 += __shfl_xor_sync(0xffffffffu, sum0, 2);
        sum1 += __shfl_xor_sync(0xffffffffu, sum1, 1);
        sum1 += __shfl_xor_sync(0xffffffffu, sum1, 2);
        float al0 = fexp(m0 - mn0), al1 = fexp(m1 - mn1);
        l0 = l0 * al0 + sum0;  m0 = mn0;
        l1 = l1 * al1 + sum1;  m1 = mn1;

        // --- O = O*alpha + P V^T, P taken from sacc via shuffles
        #pragma unroll
        for (int nt = 0; nt < 8; nt++) {
            oacc[nt][0] *= al0; oacc[nt][1] *= al0;
            oacc[nt][2] *= al1; oacc[nt][3] *= al1;
        }
        #pragma unroll
        for (int ks = 0; ks < 16; ks++) {
            // remap C-frag (cols 2tig,2tig+1) -> A-frag (cols tig, tig+4)
            float x0 = __shfl_sync(0xffffffffu, sacc[ks][0], Lsrc);
            float x1 = __shfl_sync(0xffffffffu, sacc[ks][1], Lsrc);
            float y0 = __shfl_sync(0xffffffffu, sacc[ks][2], Lsrc);
            float y1 = __shfl_sync(0xffffffffu, sacc[ks][3], Lsrc);
            float z0 = __shfl_sync(0xffffffffu, sacc[ks][0], Lsrc + 2);
            float z1 = __shfl_sync(0xffffffffu, sacc[ks][1], Lsrc + 2);
            float w0 = __shfl_sync(0xffffffffu, sacc[ks][2], Lsrc + 2);
            float w1 = __shfl_sync(0xffffffffu, sacc[ks][3], Lsrc + 2);
            uint32_t af[4];
            af[0] = cvt_tf32(hi ? x1 : x0);   // (r0, 8ks+tig)
            af[1] = cvt_tf32(hi ? y1 : y0);   // (r1, 8ks+tig)
            af[2] = cvt_tf32(hi ? z1 : z0);   // (r0, 8ks+tig+4)
            af[3] = cvt_tf32(hi ? w1 : w0);   // (r1, 8ks+tig+4)
            const int k = ks << 3;
            #pragma unroll
            for (int nt = 0; nt < 8; nt++) {
                int cc = (nt << 3) + gid;
                uint32_t bfr[2];
                bfr[0] = __float_as_uint(Vs[cc * VST + k + tig]);
                bfr[1] = __float_as_uint(Vs[cc * VST + k + tig + 4]);
                mma_tf32(oacc[nt], af, bfr);
            }
        }
        __syncthreads();   // all warps done reading Ks/Vs

        // --- load next K/V tile
        if (s0 + 128 < NL) {
            #pragma unroll
            for (int i = 0; i < 8; i++) {
                int c = lc + i * 8;
                float4 kv = *(const float4*)&kp[(size_t)c * NL + s0 + 128 + lcol];
                float4 vv = *(const float4*)&vp[(size_t)c * NL + s0 + 128 + lcol];
                uint4 ok, ov;
                ok.x = cvt_tf32(kv.x); ok.y = cvt_tf32(kv.y);
                ok.z = cvt_tf32(kv.z); ok.w = cvt_tf32(kv.w);
                ov.x = cvt_tf32(vv.x); ov.y = cvt_tf32(vv.y);
                ov.z = cvt_tf32(vv.z); ov.w = cvt_tf32(vv.w);
                *(uint4*)&Ks[c * QST + lcol] = ok;
                *(uint4*)&Vs[c * VST + lcol] = ov;
            }
        }
    }

    // epilogue: divide by l, write TRANSPOSED tf32 a_t[b][t0+t][hh*64 + c]
    float inv0 = 1.0f / l0, inv1 = 1.0f / l1;
    float* op = g_at + ((size_t)bi * NL + t0) * NC + hh * 64;
    #pragma unroll
    for (int nt = 0; nt < 8; nt++) {
        int c0 = (nt << 3) + (tig << 1);
        float2 o0, o1;
        o0.x = cvt_tf32f(oacc[nt][0] * inv0); o0.y = cvt_tf32f(oacc[nt][1] * inv0);
        o1.x = cvt_tf32f(oacc[nt][2] * inv1); o1.y = cvt_tf32f(oacc[nt][3] * inv1);
        *(float2*)&op[(size_t)r0 * NC + c0] = o0;
        *(float2*)&op[(size_t)r1 * NC + c0] = o1;
    }
}

// ---------------------------------------------------------------------------
extern "C" void kernel_launch(void* const* d_in, const int* in_sizes, int n_in,
                              void* d_out, int out_size) {
    const float* x     = (const float*)d_in[0];
    const float* nw    = (const float*)d_in[1];
    const float* nb    = (const float*)d_in[2];
    const float* wqkv  = (const float*)d_in[3];
    const float* bqkv  = (const float*)d_in[4];
    const float* wproj = (const float*)d_in[5];
    const float* bproj = (const float*)d_in[6];
    float* out = (float*)d_out;

    float *pht, *pq, *pat, *pwt;
    cudaGetSymbolAddress((void**)&pht, g_ht);
    cudaGetSymbolAddress((void**)&pq,  g_qkv);
    cudaGetSymbolAddress((void**)&pat, g_at);
    cudaGetSymbolAddress((void**)&pwt, g_wt);

    cvt_w_kernel<<<768, 256>>>(wqkv,  pwt,                    NO3 * NC / 4);
    cvt_w_kernel<<<256, 256>>>(wproj, pwt + (size_t)NO3 * NC, NC * NC / 4);
    gn_kernel<<<512, 256>>>(x, nw, nb);

    cudaFuncSetAttribute(tc_gemm,
                         cudaFuncAttributeMaxDynamicSharedMemorySize, GEMM_SMEM);
    tc_gemm<<<dim3(8, 12, 16), 256, GEMM_SMEM>>>(pwt, bqkv, pht, pq, NO3);

    cudaFuncSetAttribute(attn_kernel,
                         cudaFuncAttributeMaxDynamicSharedMemorySize, ATTN_SMEM);
    attn_kernel<<<dim3(8, 128), 256, ATTN_SMEM>>>();

    tc_gemm<<<dim3(8, 4, 16), 256, GEMM_SMEM>>>(pwt + (size_t)NO3 * NC, bproj,
                                                pat, out, NC);
}

// round 10
// speedup vs baseline: 1.5774x; 1.0863x over previous
#include <cuda_runtime.h>
#include <cstdint>
#include <math.h>

// Problem constants: B=16, C=512, L=1024 (32x32), 32 groups, 8 heads, ch=64.
#define NB   16
#define NC   512
#define NL   1024
#define NO3  1536

// Scratch (device globals; no allocation allowed)
__device__ float g_ht [(size_t)NB * NL * NC];    // groupnorm out, [b][l][c], tf32 bits
__device__ float g_qkv[(size_t)NB * NO3 * NL];   // [b][o][l], tf32 bits (Q pre-scaled)
__device__ float g_at [(size_t)NB * NL * NC];    // attention out, [b][l][c], tf32 bits
__device__ float g_wt [(size_t)(NO3 + NC) * NC]; // weights, tf32 bits (Q rows pre-scaled)
__device__ float g_bq [NO3];                     // qkv bias, Q rows pre-scaled

// ===========================================================================
// helpers
// ===========================================================================
__device__ __forceinline__ uint32_t cvt_tf32(float x) {
    uint32_t r;
    asm("cvt.rna.tf32.f32 %0, %1;" : "=r"(r) : "f"(x));
    return r;
}
__device__ __forceinline__ float cvt_tf32f(float x) {
    return __uint_as_float(cvt_tf32(x));
}
__device__ __forceinline__ void mma_tf32(float* d, const uint32_t* a,
                                         const uint32_t* b) {
    asm volatile(
        "mma.sync.aligned.m16n8k8.row.col.f32.tf32.tf32.f32 "
        "{%0,%1,%2,%3}, {%4,%5,%6,%7}, {%8,%9}, {%0,%1,%2,%3};"
        : "+f"(d[0]), "+f"(d[1]), "+f"(d[2]), "+f"(d[3])
        : "r"(a[0]), "r"(a[1]), "r"(a[2]), "r"(a[3]), "r"(b[0]), "r"(b[1]));
}
#define CP_ASYNC16(dst, src) \
    asm volatile("cp.async.cg.shared.global [%0], [%1], 16;" \
                 :: "r"(dst), "l"(src) : "memory")
#define CP_COMMIT() asm volatile("cp.async.commit_group;" ::: "memory")
#define CP_WAIT(n)  asm volatile("cp.async.wait_group %0;" :: "n"(n) : "memory")

__device__ __forceinline__ uint32_t smem_u32(const void* p) {
    uint32_t a;
    asm("{ .reg .u64 t; cvta.to.shared.u64 t, %1; cvt.u32.u64 %0, t; }"
        : "=r"(a) : "l"(p));
    return a;
}

// fast exp on FMA pipe. x <= 0 expected.
__device__ __forceinline__ float fexp(float x) {
    float y = x * 1.4426950408889634f;
    y = fmaxf(y, -125.0f);
    int   e = __float2int_rd(y);
    float f = y - (float)e;
    float p = fmaf(0.0013333558f, f, 0.0096181291f);
    p = fmaf(p, f, 0.0555041087f);
    p = fmaf(p, f, 0.2402264758f);
    p = fmaf(p, f, 0.6931471806f);
    p = fmaf(p, f, 1.0f);
    return p * __int_as_float((e + 127) << 23);
}

// ---------------------------------------------------------------------------
// Pre-round weights to tf32 bits; optionally scale Q rows (row%192 < 64)
// by 0.125 (softmax scale folded into the QKV projection).
// ---------------------------------------------------------------------------
__global__ __launch_bounds__(256) void cvt_w_kernel(const float* __restrict__ src,
                                                    float* __restrict__ dst,
                                                    int n4, int qmode) {
    int i = blockIdx.x * 256 + threadIdx.x;
    if (i < n4) {
        float s = 1.0f;
        if (qmode) {
            int row = i >> 7;                 // NC/4 = 128 float4 per row
            s = ((row % 192) < 64) ? 0.125f : 1.0f;
        }
        float4 v = ((const float4*)src)[i];
        v.x = cvt_tf32f(v.x * s); v.y = cvt_tf32f(v.y * s);
        v.z = cvt_tf32f(v.z * s); v.w = cvt_tf32f(v.w * s);
        ((float4*)dst)[i] = v;
    }
}

__global__ __launch_bounds__(256) void bias_q_kernel(const float* __restrict__ b) {
    int i = blockIdx.x * 256 + threadIdx.x;
    if (i < NO3) g_bq[i] = b[i] * (((i % 192) < 64) ? 0.125f : 1.0f);
}

// ---------------------------------------------------------------------------
// GroupNorm: one block per (batch, group); writes TRANSPOSED h_t[b][l][c],
// tf32-rounded bits (GEMM consumes directly).
// ---------------------------------------------------------------------------
__global__ __launch_bounds__(256) void gn_kernel(const float* __restrict__ x,
                                                 const float* __restrict__ w,
                                                 const float* __restrict__ b) {
    const int blk = blockIdx.x;
    const int bi  = blk >> 5;
    const int g   = blk & 31;
    const float* xg = x + ((size_t)bi * NC + (size_t)g * 16) * NL;
    const int tid = threadIdx.x;

    float s = 0.f, s2 = 0.f;
    for (int v = tid; v < 4096; v += 256) {
        float4 q = *(const float4*)(xg + (size_t)v * 4);
        s  += q.x + q.y + q.z + q.w;
        s2 += q.x*q.x + q.y*q.y + q.z*q.z + q.w*q.w;
    }
    #pragma unroll
    for (int d = 16; d; d >>= 1) {
        s  += __shfl_xor_sync(0xffffffffu, s,  d);
        s2 += __shfl_xor_sync(0xffffffffu, s2, d);
    }
    __shared__ float rs[8], rs2[8];
    __shared__ float smean, srstd;
    if ((tid & 31) == 0) { rs[tid >> 5] = s; rs2[tid >> 5] = s2; }
    __syncthreads();
    if (tid == 0) {
        float ts = 0.f, ts2 = 0.f;
        #pragma unroll
        for (int i = 0; i < 8; i++) { ts += rs[i]; ts2 += rs2[i]; }
        float mean = ts * (1.0f / 16384.0f);
        float var  = ts2 * (1.0f / 16384.0f) - mean * mean;
        smean = mean;
        srstd = rsqrtf(var + 1e-5f);
    }
    __syncthreads();
    const float mean = smean, rstd = srstd;

    const float* xb = x + (size_t)bi * NC * NL;
    float* ob = g_ht + (size_t)bi * NL * NC;
    #pragma unroll
    for (int t = 0; t < 4; t++) {
        int idx = tid + t * 256;
        int l   = (idx & 255) << 2;
        int cb  = g * 16 + ((idx >> 8) << 2);
        float vin[4][4];
        float wc[4], bc[4];
        #pragma unroll
        for (int i = 0; i < 4; i++) {
            *(float4*)vin[i] = *(const float4*)&xb[(size_t)(cb + i) * NL + l];
            wc[i] = w[cb + i] * rstd;
            bc[i] = b[cb + i];
        }
        #pragma unroll
        for (int j = 0; j < 4; j++) {
            float4 o;
            o.x = cvt_tf32f((vin[0][j] - mean) * wc[0] + bc[0]);
            o.y = cvt_tf32f((vin[1][j] - mean) * wc[1] + bc[1]);
            o.z = cvt_tf32f((vin[2][j] - mean) * wc[2] + bc[2]);
            o.w = cvt_tf32f((vin[3][j] - mean) * wc[3] + bc[3]);
            *(float4*)&ob[(size_t)(l + j) * NC + cb] = o;
        }
    }
}

// ---------------------------------------------------------------------------
// mma.sync tf32 GEMM + bias. rnd=1 -> outputs tf32-rounded bits.
// ---------------------------------------------------------------------------
#define AST 40
#define TILE_F (128 * AST)
#define GEMM_SMEM (4 * TILE_F * 4)            // 81920 B

__global__ __launch_bounds__(256, 2) void tc_gemm(const float* __restrict__ W,
                                                  const float* __restrict__ bias,
                                                  const float* __restrict__ Xt,
                                                  float* __restrict__ Y,
                                                  int M, int rnd) {
    extern __shared__ float smf[];
    const int tid  = threadIdx.x;
    const int wid  = tid >> 5;
    const int lane = tid & 31;
    const int gid  = lane >> 2;
    const int tig  = lane & 3;
    const int K    = NC;
    const int n_blk = blockIdx.x << 7;
    const int m_blk = blockIdx.y << 7;
    const float* Xb = Xt + (size_t)blockIdx.z * NL * K;
    float*       Yb = Y  + (size_t)blockIdx.z * M * NL;
    const int wm = (wid >> 1) << 5;
    const int wn = (wid & 1) << 6;

    const int lrow = tid >> 3;
    const int lkg  = (tid & 7) << 2;
    const uint32_t sbase = smem_u32(smf);

    float acc[2][8][4];
    #pragma unroll
    for (int a = 0; a < 2; a++)
        #pragma unroll
        for (int b = 0; b < 8; b++)
            #pragma unroll
            for (int c = 0; c < 4; c++) acc[a][b][c] = 0.f;

    const int nkt = K / 32;
    {
        const float* wp = W  + (size_t)(m_blk + lrow) * K + lkg;
        const float* xp = Xb + (size_t)(n_blk + lrow) * K + lkg;
        #pragma unroll
        for (int i = 0; i < 4; i++) {
            uint32_t da = sbase + ((lrow + i * 32) * AST + lkg) * 4;
            uint32_t db = da + TILE_F * 4;
            CP_ASYNC16(da, wp + (size_t)i * 32 * K);
            CP_ASYNC16(db, xp + (size_t)i * 32 * K);
        }
        CP_COMMIT();
    }

    for (int kt = 0; kt < nkt; kt++) {
        const int bf = kt & 1;
        if (kt + 1 < nkt) {
            const int k0 = (kt + 1) << 5;
            const float* wp = W  + (size_t)(m_blk + lrow) * K + k0 + lkg;
            const float* xp = Xb + (size_t)(n_blk + lrow) * K + k0 + lkg;
            uint32_t base = sbase + (((kt + 1) & 1) ? 2 * TILE_F * 4 : 0);
            #pragma unroll
            for (int i = 0; i < 4; i++) {
                uint32_t da = base + ((lrow + i * 32) * AST + lkg) * 4;
                uint32_t db = da + TILE_F * 4;
                CP_ASYNC16(da, wp + (size_t)i * 32 * K);
                CP_ASYNC16(db, xp + (size_t)i * 32 * K);
            }
            CP_COMMIT();
            CP_WAIT(1);
        } else {
            CP_WAIT(0);
        }
        __syncthreads();

        const float* As = smf + (bf ? 2 * TILE_F : 0);
        const float* Bs = As + TILE_F;
        #pragma unroll
        for (int ks = 0; ks < 4; ks++) {
            const int k = ks << 3;
            uint32_t af[2][4];
            #pragma unroll
            for (int mt = 0; mt < 2; mt++) {
                int r0 = wm + (mt << 4) + gid;
                af[mt][0] = __float_as_uint(As[r0 * AST + k + tig]);
                af[mt][1] = __float_as_uint(As[(r0 + 8) * AST + k + tig]);
                af[mt][2] = __float_as_uint(As[r0 * AST + k + tig + 4]);
                af[mt][3] = __float_as_uint(As[(r0 + 8) * AST + k + tig + 4]);
            }
            #pragma unroll
            for (int nt = 0; nt < 8; nt++) {
                int n0 = wn + (nt << 3) + gid;
                uint32_t bfr[2];
                bfr[0] = __float_as_uint(Bs[n0 * AST + k + tig]);
                bfr[1] = __float_as_uint(Bs[n0 * AST + k + tig + 4]);
                mma_tf32(acc[0][nt], af[0], bfr);
                mma_tf32(acc[1][nt], af[1], bfr);
            }
        }
        __syncthreads();
    }

    #pragma unroll
    for (int mt = 0; mt < 2; mt++) {
        int m = m_blk + wm + (mt << 4) + gid;
        float bv0 = bias[m], bv1 = bias[m + 8];
        #pragma unroll
        for (int nt = 0; nt < 8; nt++) {
            int n = n_blk + wn + (nt << 3) + (tig << 1);
            float2 o0, o1;
            if (rnd) {
                o0.x = cvt_tf32f(acc[mt][nt][0] + bv0);
                o0.y = cvt_tf32f(acc[mt][nt][1] + bv0);
                o1.x = cvt_tf32f(acc[mt][nt][2] + bv1);
                o1.y = cvt_tf32f(acc[mt][nt][3] + bv1);
            } else {
                o0.x = acc[mt][nt][0] + bv0; o0.y = acc[mt][nt][1] + bv0;
                o1.x = acc[mt][nt][2] + bv1; o1.y = acc[mt][nt][3] + bv1;
            }
            *(float2*)&Yb[(size_t)m * NL + n]       = o0;
            *(float2*)&Yb[(size_t)(m + 8) * NL + n] = o1;
        }
    }
}

// ---------------------------------------------------------------------------
// Flash attention, mma.sync tf32, register-P, fully async K/V pipeline.
// qkv is tf32-rounded with Q pre-scaled, so all loads are raw cp.async.
// Per tile: wait K -> QK -> sync -> issue K(next) -> softmax(regs) ->
//           wait V -> sync -> PV -> sync -> issue V(next).
// smem = Q(64x136) + K(64x136) + V(64x132) = 103,424 B  ->  2 CTAs/SM.
// ---------------------------------------------------------------------------
#define QST 136
#define VST 132
#define ATTN_SMEM ((2 * 64 * QST + 64 * VST) * 4)

__global__ __launch_bounds__(256, 2) void attn_kernel() {
    extern __shared__ float sm[];
    float* Qs = sm;                     // 64 x 136  [c][t]
    float* Ks = Qs + 64 * QST;          // 64 x 136  [c][s]
    float* Vs = Ks + 64 * QST;          // 64 x 132  [c][s]

    const int head = blockIdx.y;
    const int bi = head >> 3, hh = head & 7;
    const int t0 = blockIdx.x << 7;
    const float* qp = g_qkv + ((size_t)bi * NO3 + (size_t)hh * 192) * NL;
    const float* kp = qp + (size_t)64 * NL;
    const float* vp = kp + (size_t)64 * NL;
    const int tid  = threadIdx.x;
    const int wid  = tid >> 5;
    const int lane = tid & 31;
    const int gid  = lane >> 2;
    const int tig  = lane & 3;
    const int tb   = wid << 4;
    const int r0   = tb + gid, r1 = r0 + 8;

    const int lc   = tid >> 5;            // c row base (8 rows per thread)
    const int lcol = (tid & 31) << 2;     // col within row

    // shuffle source lanes for C-frag -> A-frag remap
    const int Lsrc = (lane & 0x1c) | (tig >> 1);
    const bool hi  = (tig & 1);

    const uint32_t sQ = smem_u32(Qs);
    const uint32_t sK = smem_u32(Ks);
    const uint32_t sV = smem_u32(Vs);

    // async prologue: G0 = Q + K0, G1 = V0
    #pragma unroll
    for (int i = 0; i < 8; i++) {
        int c = lc + i * 8;
        CP_ASYNC16(sQ + (uint32_t)(c * QST + lcol) * 4,
                   qp + (size_t)c * NL + t0 + lcol);
        CP_ASYNC16(sK + (uint32_t)(c * QST + lcol) * 4,
                   kp + (size_t)c * NL + lcol);
    }
    CP_COMMIT();
    #pragma unroll
    for (int i = 0; i < 8; i++) {
        int c = lc + i * 8;
        CP_ASYNC16(sV + (uint32_t)(c * VST + lcol) * 4,
                   vp + (size_t)c * NL + lcol);
    }
    CP_COMMIT();

    float m0 = -1e30f, m1 = -1e30f, l0 = 0.f, l1 = 0.f;
    float oacc[8][4];
    #pragma unroll
    for (int i = 0; i < 8; i++)
        #pragma unroll
        for (int j = 0; j < 4; j++) oacc[i][j] = 0.f;

    for (int it = 0; it < 8; it++) {
        const int s0 = it << 7;
        CP_WAIT(1);        // K(it) (+Q on it=0) landed; V(it) may be in flight
        __syncthreads();

        // --- S = Q^T K
        float sacc[16][4];
        #pragma unroll
        for (int i = 0; i < 16; i++)
            #pragma unroll
            for (int j = 0; j < 4; j++) sacc[i][j] = 0.f;
        #pragma unroll
        for (int ks = 0; ks < 8; ks++) {
            const int k = ks << 3;
            uint32_t af[4];
            af[0] = __float_as_uint(Qs[(k + tig) * QST + tb + gid]);
            af[1] = __float_as_uint(Qs[(k + tig) * QST + tb + gid + 8]);
            af[2] = __float_as_uint(Qs[(k + tig + 4) * QST + tb + gid]);
            af[3] = __float_as_uint(Qs[(k + tig + 4) * QST + tb + gid + 8]);
            #pragma unroll
            for (int nt = 0; nt < 16; nt++) {
                int sc = (nt << 3) + gid;
                uint32_t bfr[2];
                bfr[0] = __float_as_uint(Ks[(k + tig) * QST + sc]);
                bfr[1] = __float_as_uint(Ks[(k + tig + 4) * QST + sc]);
                mma_tf32(sacc[nt], af, bfr);
            }
        }
        __syncthreads();   // all warps done reading Ks

        // --- issue K(it+1): overlaps softmax + V-wait + PV
        if (it < 7) {
            #pragma unroll
            for (int i = 0; i < 8; i++) {
                int c = lc + i * 8;
                CP_ASYNC16(sK + (uint32_t)(c * QST + lcol) * 4,
                           kp + (size_t)c * NL + s0 + 128 + lcol);
            }
            CP_COMMIT();
        }

        // --- online softmax (row state in registers)
        float mx0 = -1e30f, mx1 = -1e30f;
        #pragma unroll
        for (int nt = 0; nt < 16; nt++) {
            mx0 = fmaxf(mx0, fmaxf(sacc[nt][0], sacc[nt][1]));
            mx1 = fmaxf(mx1, fmaxf(sacc[nt][2], sacc[nt][3]));
        }
        mx0 = fmaxf(mx0, __shfl_xor_sync(0xffffffffu, mx0, 1));
        mx0 = fmaxf(mx0, __shfl_xor_sync(0xffffffffu, mx0, 2));
        mx1 = fmaxf(mx1, __shfl_xor_sync(0xffffffffu, mx1, 1));
        mx1 = fmaxf(mx1, __shfl_xor_sync(0xffffffffu, mx1, 2));
        float mn0 = fmaxf(m0, mx0), mn1 = fmaxf(m1, mx1);
        float sum0 = 0.f, sum1 = 0.f;
        #pragma unroll
        for (int nt = 0; nt < 16; nt++) {
            float p0 = fexp(sacc[nt][0] - mn0);
            float p1 = fexp(sacc[nt][1] - mn0);
            float p2 = fexp(sacc[nt][2] - mn1);
            float p3 = fexp(sacc[nt][3] - mn1);
            sum0 += p0 + p1; sum1 += p2 + p3;
            sacc[nt][0] = p0; sacc[nt][1] = p1;
            sacc[nt][2] = p2; sacc[nt][3] = p3;
        }
        sum0 += __shfl_xor_sync(0xffffffffu, sum0, 1);
        sum0 += __shfl_xor_sync(0xffffffffu, sum0, 2);
        sum1 += __shfl_xor_sync(0xffffffffu, sum1, 1);
        sum1 += __shfl_xor_sync(0xffffffffu, sum1, 2);
        float al0 = fexp(m0 - mn0), al1 = fexp(m1 - mn1);
        l0 = l0 * al0 + sum0;  m0 = mn0;
        l1 = l1 * al1 + sum1;  m1 = mn1;

        // --- wait V(it)  (outstanding: K(it+1) only, except last tile)
        if (it < 7) { CP_WAIT(1); } else { CP_WAIT(0); }
        __syncthreads();

        // --- O = O*alpha + P V^T, P from sacc via shuffles
        #pragma unroll
        for (int nt = 0; nt < 8; nt++) {
            oacc[nt][0] *= al0; oacc[nt][1] *= al0;
            oacc[nt][2] *= al1; oacc[nt][3] *= al1;
        }
        #pragma unroll
        for (int ks = 0; ks < 16; ks++) {
            float x0 = __shfl_sync(0xffffffffu, sacc[ks][0], Lsrc);
            float x1 = __shfl_sync(0xffffffffu, sacc[ks][1], Lsrc);
            float y0 = __shfl_sync(0xffffffffu, sacc[ks][2], Lsrc);
            float y1 = __shfl_sync(0xffffffffu, sacc[ks][3], Lsrc);
            float z0 = __shfl_sync(0xffffffffu, sacc[ks][0], Lsrc + 2);
            float z1 = __shfl_sync(0xffffffffu, sacc[ks][1], Lsrc + 2);
            float w0 = __shfl_sync(0xffffffffu, sacc[ks][2], Lsrc + 2);
            float w1 = __shfl_sync(0xffffffffu, sacc[ks][3], Lsrc + 2);
            uint32_t af[4];
            af[0] = cvt_tf32(hi ? x1 : x0);
            af[1] = cvt_tf32(hi ? y1 : y0);
            af[2] = cvt_tf32(hi ? z1 : z0);
            af[3] = cvt_tf32(hi ? w1 : w0);
            const int k = ks << 3;
            #pragma unroll
            for (int nt = 0; nt < 8; nt++) {
                int cc = (nt << 3) + gid;
                uint32_t bfr[2];
                bfr[0] = __float_as_uint(Vs[cc * VST + k + tig]);
                bfr[1] = __float_as_uint(Vs[cc * VST + k + tig + 4]);
                mma_tf32(oacc[nt], af, bfr);
            }
        }
        __syncthreads();   // all warps done reading Vs

        // --- issue V(it+1): overlaps next tile's QK + softmax
        if (it < 7) {
            #pragma unroll
            for (int i = 0; i < 8; i++) {
                int c = lc + i * 8;
                CP_ASYNC16(sV + (uint32_t)(c * VST + lcol) * 4,
                           vp + (size_t)c * NL + s0 + 128 + lcol);
            }
            CP_COMMIT();
        }
    }

    // epilogue: divide by l, write TRANSPOSED tf32 a_t[b][t0+t][hh*64 + c]
    float inv0 = 1.0f / l0, inv1 = 1.0f / l1;
    float* op = g_at + ((size_t)bi * NL + t0) * NC + hh * 64;
    #pragma unroll
    for (int nt = 0; nt < 8; nt++) {
        int c0 = (nt << 3) + (tig << 1);
        float2 o0, o1;
        o0.x = cvt_tf32f(oacc[nt][0] * inv0); o0.y = cvt_tf32f(oacc[nt][1] * inv0);
        o1.x = cvt_tf32f(oacc[nt][2] * inv1); o1.y = cvt_tf32f(oacc[nt][3] * inv1);
        *(float2*)&op[(size_t)r0 * NC + c0] = o0;
        *(float2*)&op[(size_t)r1 * NC + c0] = o1;
    }
}

// ---------------------------------------------------------------------------
extern "C" void kernel_launch(void* const* d_in, const int* in_sizes, int n_in,
                              void* d_out, int out_size) {
    const float* x     = (const float*)d_in[0];
    const float* nw    = (const float*)d_in[1];
    const float* nb    = (const float*)d_in[2];
    const float* wqkv  = (const float*)d_in[3];
    const float* bqkv  = (const float*)d_in[4];
    const float* wproj = (const float*)d_in[5];
    const float* bproj = (const float*)d_in[6];
    float* out = (float*)d_out;

    float *pht, *pq, *pat, *pwt, *pbq;
    cudaGetSymbolAddress((void**)&pht, g_ht);
    cudaGetSymbolAddress((void**)&pq,  g_qkv);
    cudaGetSymbolAddress((void**)&pat, g_at);
    cudaGetSymbolAddress((void**)&pwt, g_wt);
    cudaGetSymbolAddress((void**)&pbq, g_bq);

    cvt_w_kernel<<<768, 256>>>(wqkv,  pwt,                    NO3 * NC / 4, 1);
    cvt_w_kernel<<<256, 256>>>(wproj, pwt + (size_t)NO3 * NC, NC * NC / 4, 0);
    bias_q_kernel<<<6, 256>>>(bqkv);
    gn_kernel<<<512, 256>>>(x, nw, nb);

    cudaFuncSetAttribute(tc_gemm,
                         cudaFuncAttributeMaxDynamicSharedMemorySize, GEMM_SMEM);
    tc_gemm<<<dim3(8, 12, 16), 256, GEMM_SMEM>>>(pwt, pbq, pht, pq, NO3, 1);

    cudaFuncSetAttribute(attn_kernel,
                         cudaFuncAttributeMaxDynamicSharedMemorySize, ATTN_SMEM);
    attn_kernel<<<dim3(8, 128), 256, ATTN_SMEM>>>();

    tc_gemm<<<dim3(8, 4, 16), 256, GEMM_SMEM>>>(pwt + (size_t)NO3 * NC, bproj,
                                                pat, out, NC, 0);
}